// round 6
// baseline (speedup 1.0000x reference)
#include <cuda_runtime.h>
#include <cuda_fp16.h>
#include <cstdint>

#define NB    8
#define CIN   128
#define SP    1600
#define NHEAD 8
#define HD    16

typedef unsigned long long u64;

// ---- packed f32x2 helpers (proj kernels) ----
__device__ __forceinline__ u64 pack2(float lo, float hi) {
    u64 r; asm("mov.b64 %0,{%1,%2};" : "=l"(r) : "f"(lo), "f"(hi)); return r;
}
__device__ __forceinline__ float2 unpack2(u64 v) {
    float2 r; asm("mov.b64 {%0,%1},%2;" : "=f"(r.x), "=f"(r.y) : "l"(v)); return r;
}
__device__ __forceinline__ u64 ffma2(u64 a, u64 b, u64 c) {
    u64 d; asm("fma.rn.f32x2 %0,%1,%2,%3;" : "=l"(d) : "l"(a), "l"(b), "l"(c)); return d;
}
__device__ __forceinline__ float ex2f(float x) {
    float y; asm("ex2.approx.f32 %0,%1;" : "=f"(y) : "f"(x)); return y;
}

// ---- fp16 helpers ----
// f16x2 word: first arg -> low 16 bits, second -> high 16 bits
__device__ __forceinline__ uint32_t f16x2_of(float lo, float hi) {
    uint32_t r;
    asm("cvt.rn.f16x2.f32 %0, %1, %2;" : "=r"(r) : "f"(hi), "f"(lo));
    return r;
}
__device__ __forceinline__ void f16x2_to_f32(uint32_t w, float& lo, float& hi) {
    asm("{ .reg .b16 l, h; mov.b32 {l, h}, %2; cvt.f32.f16 %0, l; cvt.f32.f16 %1, h; }"
        : "=f"(lo), "=f"(hi) : "r"(w));
}
// split (a,b) -> main f16x2 word + residual f16x2 word, packed into u64
__device__ __forceinline__ u64 packh2(float a, float b) {
    uint32_t hw = f16x2_of(a, b);
    float ha, hb;
    f16x2_to_f32(hw, ha, hb);
    uint32_t lw = f16x2_of(a - ha, b - hb);
    return (u64)hw | ((u64)lw << 32);
}

// warp mma: D += A(f16 16x16) * B(f16 16x8), f32 accum (portable, sm_80+)
__device__ __forceinline__ void mmaf16(float* d, const uint32_t* a, const uint32_t* b) {
    asm volatile("mma.sync.aligned.m16n8k16.row.col.f32.f16.f16.f32 "
        "{%0,%1,%2,%3},{%4,%5,%6,%7},{%8,%9},{%0,%1,%2,%3};"
        : "+f"(d[0]), "+f"(d[1]), "+f"(d[2]), "+f"(d[3])
        : "r"(a[0]), "r"(a[1]), "r"(a[2]), "r"(a[3]), "r"(b[0]), "r"(b[1]));
}

// Packed scratch per (n,h) = nh in [0,64):
//  g_qpk: [nh][8 dpairs][1600]  u32  = f16x2(q[2dp], q[2dp+1])  (pre-scaled)
//  g_kpk: [nh][8 dpairs][1600]  u64  = kh_f16x2 | kl_f16x2<<32
//  g_vpk: [nh][800 keypairs][16 dims] u64 = vh | vl<<32
__device__ uint32_t g_qpk[(size_t)64 * 8 * SP];
__device__ u64      g_kpk[(size_t)64 * 8 * SP];
__device__ u64      g_vpk[(size_t)64 * 800 * 16];
__device__ float    g_att[(size_t)NB * CIN * SP];

// ===================================================================
// QKV projection + fp16 pack epilogue.
// ===================================================================
__global__ void proj_qkv_pack(const float* __restrict__ W,
                              const float* __restrict__ X) {
    __shared__ float Ws[16][64 + 4];
    __shared__ float Xs[16][64 + 4];

    const int n  = blockIdx.z;
    const int s0 = blockIdx.x * 64;
    const int o0 = blockIdx.y * 64;
    const int tx = threadIdx.x, ty = threadIdx.y;
    const int tid = ty * 16 + tx;
    const float* Xn = X + (size_t)n * CIN * SP;

    u64 acc2[2][4];
    #pragma unroll
    for (int p = 0; p < 2; p++)
        #pragma unroll
        for (int j = 0; j < 4; j++) acc2[p][j] = 0ull;

    for (int k0 = 0; k0 < CIN; k0 += 16) {
        #pragma unroll
        for (int r = 0; r < 4; r++) {
            int idx = tid + r * 256;
            int oo = idx >> 4, kc = idx & 15;
            Ws[kc][oo] = W[(size_t)(o0 + oo) * CIN + k0 + kc];
            int kc2 = idx >> 6, ss = idx & 63;
            Xs[kc2][ss] = Xn[(size_t)(k0 + kc2) * SP + s0 + ss];
        }
        __syncthreads();
        #pragma unroll
        for (int kc = 0; kc < 16; kc++) {
            ulonglong2 wv = *(const ulonglong2*)&Ws[kc][ty * 4];
            float4 xv = *(const float4*)&Xs[kc][tx * 4];
            u64 x0 = pack2(xv.x, xv.x), x1 = pack2(xv.y, xv.y);
            u64 x2 = pack2(xv.z, xv.z), x3 = pack2(xv.w, xv.w);
            acc2[0][0] = ffma2(wv.x, x0, acc2[0][0]);
            acc2[0][1] = ffma2(wv.x, x1, acc2[0][1]);
            acc2[0][2] = ffma2(wv.x, x2, acc2[0][2]);
            acc2[0][3] = ffma2(wv.x, x3, acc2[0][3]);
            acc2[1][0] = ffma2(wv.y, x0, acc2[1][0]);
            acc2[1][1] = ffma2(wv.y, x1, acc2[1][1]);
            acc2[1][2] = ffma2(wv.y, x2, acc2[1][2]);
            acc2[1][3] = ffma2(wv.y, x3, acc2[1][3]);
        }
        __syncthreads();
    }

    const float qs = 0.25f * 1.4426950408889634f;  // attn scale * log2(e)

    #pragma unroll
    for (int p = 0; p < 2; p++) {
        int o = o0 + ty * 4 + 2 * p;       // even
        int hh = o / 48;
        int within = o - hh * 48;          // even
        int nhI = n * 8 + hh;
        float r0[4], r1[4];
        #pragma unroll
        for (int j = 0; j < 4; j++) {
            float2 v = unpack2(acc2[p][j]);
            r0[j] = v.x;                   // dim `within`
            r1[j] = v.y;                   // dim `within+1`
        }
        if (within < 16) {
            // Q: plain fp16 word per (dpair, token), pre-scaled
            int dp = within >> 1;
            uint32_t* dst = g_qpk + ((size_t)nhI * 8 + dp) * SP + s0 + tx * 4;
            #pragma unroll
            for (int j = 0; j < 4; j++)
                dst[j] = f16x2_of(r0[j] * qs, r1[j] * qs);
        } else if (within < 32) {
            // K: hi/lo split u64 per (dpair, token)
            int dp = (within - 16) >> 1;
            u64* dst = g_kpk + ((size_t)nhI * 8 + dp) * SP + s0 + tx * 4;
            #pragma unroll
            for (int j = 0; j < 4; j++)
                dst[j] = packh2(r0[j], r1[j]);
        } else {
            // V transpose: u64 per (keypair, dim)
            int dl = within - 32;
            int sp = (s0 + tx * 4) >> 1;
            u64* vb = g_vpk + (size_t)nhI * 800 * 16;
            vb[(size_t)sp * 16 + dl]           = packh2(r0[0], r0[1]);
            vb[(size_t)sp * 16 + dl + 1]       = packh2(r1[0], r1[1]);
            vb[(size_t)(sp + 1) * 16 + dl]     = packh2(r0[2], r0[3]);
            vb[(size_t)(sp + 1) * 16 + dl + 1] = packh2(r1[2], r1[3]);
        }
    }
}

// ===================================================================
// Output projection (FFMA2, with bias).
// ===================================================================
__global__ void proj_out(const float* __restrict__ W,
                         const float* __restrict__ X,
                         const float* __restrict__ bias,
                         float* __restrict__ Y) {
    __shared__ float Ws[16][64 + 4];
    __shared__ float Xs[16][64 + 4];

    const int n  = blockIdx.z;
    const int s0 = blockIdx.x * 64;
    const int o0 = blockIdx.y * 64;
    const int tx = threadIdx.x, ty = threadIdx.y;
    const int tid = ty * 16 + tx;
    const float* Xn = X + (size_t)n * CIN * SP;

    u64 acc2[2][4];
    #pragma unroll
    for (int p = 0; p < 2; p++)
        #pragma unroll
        for (int j = 0; j < 4; j++) acc2[p][j] = 0ull;

    for (int k0 = 0; k0 < CIN; k0 += 16) {
        #pragma unroll
        for (int r = 0; r < 4; r++) {
            int idx = tid + r * 256;
            int oo = idx >> 4, kc = idx & 15;
            Ws[kc][oo] = W[(size_t)(o0 + oo) * CIN + k0 + kc];
            int kc2 = idx >> 6, ss = idx & 63;
            Xs[kc2][ss] = Xn[(size_t)(k0 + kc2) * SP + s0 + ss];
        }
        __syncthreads();
        #pragma unroll
        for (int kc = 0; kc < 16; kc++) {
            ulonglong2 wv = *(const ulonglong2*)&Ws[kc][ty * 4];
            float4 xv = *(const float4*)&Xs[kc][tx * 4];
            u64 x0 = pack2(xv.x, xv.x), x1 = pack2(xv.y, xv.y);
            u64 x2 = pack2(xv.z, xv.z), x3 = pack2(xv.w, xv.w);
            acc2[0][0] = ffma2(wv.x, x0, acc2[0][0]);
            acc2[0][1] = ffma2(wv.x, x1, acc2[0][1]);
            acc2[0][2] = ffma2(wv.x, x2, acc2[0][2]);
            acc2[0][3] = ffma2(wv.x, x3, acc2[0][3]);
            acc2[1][0] = ffma2(wv.y, x0, acc2[1][0]);
            acc2[1][1] = ffma2(wv.y, x1, acc2[1][1]);
            acc2[1][2] = ffma2(wv.y, x2, acc2[1][2]);
            acc2[1][3] = ffma2(wv.y, x3, acc2[1][3]);
        }
        __syncthreads();
    }

    #pragma unroll
    for (int p = 0; p < 2; p++) {
        int o = o0 + ty * 4 + 2 * p;
        float b0 = bias[o], b1 = bias[o + 1];
        float r0[4], r1[4];
        #pragma unroll
        for (int j = 0; j < 4; j++) {
            float2 v = unpack2(acc2[p][j]);
            r0[j] = v.x + b0; r1[j] = v.y + b1;
        }
        float* y0 = Y + ((size_t)n * CIN + o) * SP + s0 + tx * 4;
        *(float4*)y0 = make_float4(r0[0], r0[1], r0[2], r0[3]);
        *(float4*)(y0 + SP) = make_float4(r1[0], r1[1], r1[2], r1[3]);
    }
}

// ===================================================================
// Attention via fp16 mma.sync: Q plain, K hi/lo, P plain, V hi/lo.
// CTA = 4 warps x 16 queries; keys in steps of 16; no SMEM.
// Fragment maps (g = lane>>2, t = lane&3):
//   A a0:(g,2t|2t+1) a1:(g+8,..) a2:(g,2t+8|..) a3:(g+8,..)
//   B b0:(2t|2t+1, g) b1:(2t+8|2t+9, g)
//   C c0:(g,2t) c1:(g,2t+1) c2:(g+8,2t) c3:(g+8,2t+1)
// ===================================================================
__global__ __launch_bounds__(128) void attn_mma(float* __restrict__ out) {
    const int tid  = threadIdx.x;
    const int warp = tid >> 5, lane = tid & 31;
    const int g = lane >> 2, t = lane & 3;
    const int nh = blockIdx.y, n = nh >> 3, h = nh & 7;
    const int q0 = blockIdx.x * 64 + warp * 16;

    const uint32_t* qp = g_qpk + (size_t)nh * 8 * SP;
    const u64* kp = g_kpk + (size_t)nh * 8 * SP;
    const u64* vp = g_vpk + (size_t)nh * 800 * 16;

    // ---- Q fragment (plain fp16)
    uint32_t aq[4];
    aq[0] = qp[(size_t)t * SP + q0 + g];
    aq[1] = qp[(size_t)t * SP + q0 + 8 + g];
    aq[2] = qp[(size_t)(t + 4) * SP + q0 + g];
    aq[3] = qp[(size_t)(t + 4) * SP + q0 + 8 + g];

    float dpv0[4] = {0.f, 0.f, 0.f, 0.f};
    float dpv1[4] = {0.f, 0.f, 0.f, 0.f};
    float ls0 = 0.f, ls1 = 0.f;

    const u64* kpa = kp + (size_t)t * SP;
    const u64* kpb = kp + (size_t)(t + 4) * SP;

    #pragma unroll 4
    for (int j0 = 0; j0 < SP; j0 += 16) {
        // ---- K fragments (4x LDG.64: main|resid)
        u64 kw00 = kpa[j0 + g],     kw10 = kpb[j0 + g];       // n-block 0
        u64 kw01 = kpa[j0 + 8 + g], kw11 = kpb[j0 + 8 + g];   // n-block 1

        float d0[4] = {0.f, 0.f, 0.f, 0.f};
        float d1[4] = {0.f, 0.f, 0.f, 0.f};
        {
            uint32_t bh[2] = {(uint32_t)kw00, (uint32_t)kw10};
            uint32_t bl[2] = {(uint32_t)(kw00 >> 32), (uint32_t)(kw10 >> 32)};
            mmaf16(d0, aq, bh);
            mmaf16(d0, aq, bl);
        }
        {
            uint32_t bh[2] = {(uint32_t)kw01, (uint32_t)kw11};
            uint32_t bl[2] = {(uint32_t)(kw01 >> 32), (uint32_t)(kw11 >> 32)};
            mmaf16(d1, aq, bh);
            mmaf16(d1, aq, bl);
        }

        // ---- softmax (log2-domain, no max) + P fragment (plain fp16)
        float p00 = ex2f(d0[0]), p01 = ex2f(d0[1]);
        float p02 = ex2f(d0[2]), p03 = ex2f(d0[3]);
        float p10 = ex2f(d1[0]), p11 = ex2f(d1[1]);
        float p12 = ex2f(d1[2]), p13 = ex2f(d1[3]);
        ls0 += p00 + p01 + p10 + p11;
        ls1 += p02 + p03 + p12 + p13;

        uint32_t pa[4];
        pa[0] = f16x2_of(p00, p01);   // (g,   keys j0+2t, j0+2t+1)
        pa[1] = f16x2_of(p02, p03);   // (g+8, ..)
        pa[2] = f16x2_of(p10, p11);   // (g,   keys j0+8+2t, ..)
        pa[3] = f16x2_of(p12, p13);   // (g+8, ..)

        // ---- V fragments (4x LDG.64) + PV
        const int spb = j0 >> 1;
        u64 v00 = vp[(size_t)(spb + t) * 16 + g];
        u64 v01 = vp[(size_t)(spb + 4 + t) * 16 + g];
        u64 v10 = vp[(size_t)(spb + t) * 16 + 8 + g];
        u64 v11 = vp[(size_t)(spb + 4 + t) * 16 + 8 + g];
        {
            uint32_t vbh[2] = {(uint32_t)v00, (uint32_t)v01};
            uint32_t vbl[2] = {(uint32_t)(v00 >> 32), (uint32_t)(v01 >> 32)};
            mmaf16(dpv0, pa, vbh);
            mmaf16(dpv0, pa, vbl);
        }
        {
            uint32_t vbh[2] = {(uint32_t)v10, (uint32_t)v11};
            uint32_t vbl[2] = {(uint32_t)(v10 >> 32), (uint32_t)(v11 >> 32)};
            mmaf16(dpv1, pa, vbh);
            mmaf16(dpv1, pa, vbl);
        }
    }

    // ---- row-sum reduce over quad
    ls0 += __shfl_xor_sync(0xFFFFFFFFu, ls0, 1);
    ls0 += __shfl_xor_sync(0xFFFFFFFFu, ls0, 2);
    ls1 += __shfl_xor_sync(0xFFFFFFFFu, ls1, 1);
    ls1 += __shfl_xor_sync(0xFFFFFFFFu, ls1, 2);
    float inv0 = 1.f / ls0, inv1 = 1.f / ls1;

    // ---- store fp32 [n][c][s]
    float* ob = out + ((size_t)n * CIN + h * HD) * SP;
    #pragma unroll
    for (int db = 0; db < 2; db++) {
        const float* dpv = db ? dpv1 : dpv0;
        int d = db * 8 + 2 * t;
        ob[(size_t)d * SP + q0 + g]           = dpv[0] * inv0;
        ob[(size_t)(d + 1) * SP + q0 + g]     = dpv[1] * inv0;
        ob[(size_t)d * SP + q0 + 8 + g]       = dpv[2] * inv1;
        ob[(size_t)(d + 1) * SP + q0 + 8 + g] = dpv[3] * inv1;
    }
}

// ===================================================================
extern "C" void kernel_launch(void* const* d_in, const int* in_sizes, int n_in,
                              void* d_out, int out_size) {
    const float* x     = (const float*)d_in[0];
    const float* w_qkv = (const float*)d_in[1];
    const float* w_o   = (const float*)d_in[2];
    const float* b_o   = (const float*)d_in[3];
    float* out = (float*)d_out;

    float* att_ptr;
    cudaGetSymbolAddress((void**)&att_ptr, g_att);

    dim3 blk(16, 16);
    proj_qkv_pack<<<dim3(SP / 64, 384 / 64, NB), blk>>>(w_qkv, x);
    attn_mma<<<dim3(25, NB * NHEAD), 128>>>(att_ptr);
    proj_out<<<dim3(SP / 64, CIN / 64, NB), blk>>>(w_o, att_ptr, b_o, out);
}

// round 7
// speedup vs baseline: 2.0504x; 2.0504x over previous
#include <cuda_runtime.h>
#include <cuda_fp16.h>
#include <cstdint>

#define NB    8
#define CIN   128
#define SP    1600
#define NHEAD 8
#define HD    16

typedef unsigned long long u64;

// ---- packed f32x2 helpers (proj kernels) ----
__device__ __forceinline__ u64 pack2(float lo, float hi) {
    u64 r; asm("mov.b64 %0,{%1,%2};" : "=l"(r) : "f"(lo), "f"(hi)); return r;
}
__device__ __forceinline__ float2 unpack2(u64 v) {
    float2 r; asm("mov.b64 {%0,%1},%2;" : "=f"(r.x), "=f"(r.y) : "l"(v)); return r;
}
__device__ __forceinline__ u64 ffma2(u64 a, u64 b, u64 c) {
    u64 d; asm("fma.rn.f32x2 %0,%1,%2,%3;" : "=l"(d) : "l"(a), "l"(b), "l"(c)); return d;
}
__device__ __forceinline__ float ex2f(float x) {
    float y; asm("ex2.approx.f32 %0,%1;" : "=f"(y) : "f"(x)); return y;
}

// f16x2 word: first arg -> low 16 bits, second -> high 16 bits
__device__ __forceinline__ uint32_t f16x2_of(float lo, float hi) {
    uint32_t r;
    asm("cvt.rn.f16x2.f32 %0, %1, %2;" : "=r"(r) : "f"(hi), "f"(lo));
    return r;
}

// warp mma: D += A(f16 16x16) * B(f16 16x8), f32 accum (portable, sm_80+)
__device__ __forceinline__ void mmaf16(float* d, const uint32_t* a, uint32_t b0, uint32_t b1) {
    asm volatile("mma.sync.aligned.m16n8k16.row.col.f32.f16.f16.f32 "
        "{%0,%1,%2,%3},{%4,%5,%6,%7},{%8,%9},{%0,%1,%2,%3};"
        : "+f"(d[0]), "+f"(d[1]), "+f"(d[2]), "+f"(d[3])
        : "r"(a[0]), "r"(a[1]), "r"(a[2]), "r"(a[3]), "r"(b0), "r"(b1));
}

// Packed scratch per (n,h) = nh in [0,64):
//  g_qpk: u32 [nh][8 dpairs][SP]          f16x2(q[2dp],q[2dp+1]) pre-scaled
//  g_kp2: u64 [nh][SP][4]   word = f16x2 K dpair t  | dpair t+4 << 32
//  g_vp2: u64 [nh][100][16][4] word = f16x2 V keypair t | keypair t+4 << 32 (per dim)
__device__ uint32_t g_qpk[(size_t)64 * 8 * SP];
__device__ u64      g_kp2[(size_t)64 * SP * 4];
__device__ u64      g_vp2[(size_t)64 * 100 * 16 * 4];
__device__ float    g_att[(size_t)NB * CIN * SP];

// ===================================================================
// QKV projection + fp16 pack epilogue (fragment-ready layouts).
// ===================================================================
__global__ void proj_qkv_pack(const float* __restrict__ W,
                              const float* __restrict__ X) {
    __shared__ float Ws[16][64 + 4];
    __shared__ float Xs[16][64 + 4];

    const int n  = blockIdx.z;
    const int s0 = blockIdx.x * 64;
    const int o0 = blockIdx.y * 64;
    const int tx = threadIdx.x, ty = threadIdx.y;
    const int tid = ty * 16 + tx;
    const float* Xn = X + (size_t)n * CIN * SP;

    u64 acc2[2][4];
    #pragma unroll
    for (int p = 0; p < 2; p++)
        #pragma unroll
        for (int j = 0; j < 4; j++) acc2[p][j] = 0ull;

    for (int k0 = 0; k0 < CIN; k0 += 16) {
        #pragma unroll
        for (int r = 0; r < 4; r++) {
            int idx = tid + r * 256;
            int oo = idx >> 4, kc = idx & 15;
            Ws[kc][oo] = W[(size_t)(o0 + oo) * CIN + k0 + kc];
            int kc2 = idx >> 6, ss = idx & 63;
            Xs[kc2][ss] = Xn[(size_t)(k0 + kc2) * SP + s0 + ss];
        }
        __syncthreads();
        #pragma unroll
        for (int kc = 0; kc < 16; kc++) {
            ulonglong2 wv = *(const ulonglong2*)&Ws[kc][ty * 4];
            float4 xv = *(const float4*)&Xs[kc][tx * 4];
            u64 x0 = pack2(xv.x, xv.x), x1 = pack2(xv.y, xv.y);
            u64 x2 = pack2(xv.z, xv.z), x3 = pack2(xv.w, xv.w);
            acc2[0][0] = ffma2(wv.x, x0, acc2[0][0]);
            acc2[0][1] = ffma2(wv.x, x1, acc2[0][1]);
            acc2[0][2] = ffma2(wv.x, x2, acc2[0][2]);
            acc2[0][3] = ffma2(wv.x, x3, acc2[0][3]);
            acc2[1][0] = ffma2(wv.y, x0, acc2[1][0]);
            acc2[1][1] = ffma2(wv.y, x1, acc2[1][1]);
            acc2[1][2] = ffma2(wv.y, x2, acc2[1][2]);
            acc2[1][3] = ffma2(wv.y, x3, acc2[1][3]);
        }
        __syncthreads();
    }

    const float qs = 0.25f * 1.4426950408889634f;  // attn scale * log2(e)

    #pragma unroll
    for (int p = 0; p < 2; p++) {
        int o = o0 + ty * 4 + 2 * p;       // even
        int hh = o / 48;
        int within = o - hh * 48;          // even
        int nhI = n * 8 + hh;
        float r0[4], r1[4];
        #pragma unroll
        for (int j = 0; j < 4; j++) {
            float2 v = unpack2(acc2[p][j]);
            r0[j] = v.x;                   // dim `within`
            r1[j] = v.y;                   // dim `within+1`
        }
        int tok0 = s0 + tx * 4;
        if (within < 16) {
            // Q: plain fp16 word per (dpair, token), pre-scaled
            int dp = within >> 1;
            uint32_t* dst = g_qpk + ((size_t)nhI * 8 + dp) * SP + tok0;
            #pragma unroll
            for (int j = 0; j < 4; j++)
                dst[j] = f16x2_of(r0[j] * qs, r1[j] * qs);
        } else if (within < 32) {
            // K: u32 halves into [tok][slot]{u64}: slot=dp&3, half=dp>>2
            int dp = (within - 16) >> 1;
            uint32_t* kb = (uint32_t*)g_kp2 + (size_t)nhI * SP * 8;
            int off = (dp & 3) * 2 + (dp >> 2);
            #pragma unroll
            for (int j = 0; j < 4; j++)
                kb[(size_t)(tok0 + j) * 8 + off] = f16x2_of(r0[j], r1[j]);
        } else {
            // V: u32 halves into [kt][dim][slot]{u64}: keypair kpl: slot=kpl&3, half=kpl>>2
            int dl = within - 32;                 // dims dl, dl+1
            uint32_t* vb = (uint32_t*)g_vp2 + (size_t)nhI * 100 * 128;
            int kt  = tok0 >> 4;
            int kpl = (tok0 >> 1) & 7;            // even
            size_t base = (size_t)kt * 128;
            vb[base + ((size_t)dl * 4 + (kpl & 3)) * 2 + (kpl >> 2)]             = f16x2_of(r0[0], r0[1]);
            vb[base + ((size_t)dl * 4 + ((kpl + 1) & 3)) * 2 + ((kpl + 1) >> 2)] = f16x2_of(r0[2], r0[3]);
            vb[base + ((size_t)(dl + 1) * 4 + (kpl & 3)) * 2 + (kpl >> 2)]             = f16x2_of(r1[0], r1[1]);
            vb[base + ((size_t)(dl + 1) * 4 + ((kpl + 1) & 3)) * 2 + ((kpl + 1) >> 2)] = f16x2_of(r1[2], r1[3]);
        }
    }
}

// ===================================================================
// Output projection (FFMA2, with bias).
// ===================================================================
__global__ void proj_out(const float* __restrict__ W,
                         const float* __restrict__ X,
                         const float* __restrict__ bias,
                         float* __restrict__ Y) {
    __shared__ float Ws[16][64 + 4];
    __shared__ float Xs[16][64 + 4];

    const int n  = blockIdx.z;
    const int s0 = blockIdx.x * 64;
    const int o0 = blockIdx.y * 64;
    const int tx = threadIdx.x, ty = threadIdx.y;
    const int tid = ty * 16 + tx;
    const float* Xn = X + (size_t)n * CIN * SP;

    u64 acc2[2][4];
    #pragma unroll
    for (int p = 0; p < 2; p++)
        #pragma unroll
        for (int j = 0; j < 4; j++) acc2[p][j] = 0ull;

    for (int k0 = 0; k0 < CIN; k0 += 16) {
        #pragma unroll
        for (int r = 0; r < 4; r++) {
            int idx = tid + r * 256;
            int oo = idx >> 4, kc = idx & 15;
            Ws[kc][oo] = W[(size_t)(o0 + oo) * CIN + k0 + kc];
            int kc2 = idx >> 6, ss = idx & 63;
            Xs[kc2][ss] = Xn[(size_t)(k0 + kc2) * SP + s0 + ss];
        }
        __syncthreads();
        #pragma unroll
        for (int kc = 0; kc < 16; kc++) {
            ulonglong2 wv = *(const ulonglong2*)&Ws[kc][ty * 4];
            float4 xv = *(const float4*)&Xs[kc][tx * 4];
            u64 x0 = pack2(xv.x, xv.x), x1 = pack2(xv.y, xv.y);
            u64 x2 = pack2(xv.z, xv.z), x3 = pack2(xv.w, xv.w);
            acc2[0][0] = ffma2(wv.x, x0, acc2[0][0]);
            acc2[0][1] = ffma2(wv.x, x1, acc2[0][1]);
            acc2[0][2] = ffma2(wv.x, x2, acc2[0][2]);
            acc2[0][3] = ffma2(wv.x, x3, acc2[0][3]);
            acc2[1][0] = ffma2(wv.y, x0, acc2[1][0]);
            acc2[1][1] = ffma2(wv.y, x1, acc2[1][1]);
            acc2[1][2] = ffma2(wv.y, x2, acc2[1][2]);
            acc2[1][3] = ffma2(wv.y, x3, acc2[1][3]);
        }
        __syncthreads();
    }

    #pragma unroll
    for (int p = 0; p < 2; p++) {
        int o = o0 + ty * 4 + 2 * p;
        float b0 = bias[o], b1 = bias[o + 1];
        float r0[4], r1[4];
        #pragma unroll
        for (int j = 0; j < 4; j++) {
            float2 v = unpack2(acc2[p][j]);
            r0[j] = v.x + b0; r1[j] = v.y + b1;
        }
        float* y0 = Y + ((size_t)n * CIN + o) * SP + s0 + tx * 4;
        *(float4*)y0 = make_float4(r0[0], r0[1], r0[2], r0[3]);
        *(float4*)(y0 + SP) = make_float4(r1[0], r1[1], r1[2], r1[3]);
    }
}

// ===================================================================
// Attention, plain fp16 mma.sync, coalesced fragment layouts.
// CTA = 4 warps x 16 queries; 16 keys/iter; 4 MMAs + 4 LDG.64 per tile.
// Fragment maps (g = lane>>2, t = lane&3):
//   A a0:(g,2t|2t+1) a1:(g+8,..) a2:(g,2t+8|..) a3:(g+8,..)
//   B b0:(2t|2t+1, g) b1:(2t+8|2t+9, g)
//   C c0:(g,2t) c1:(g,2t+1) c2:(g+8,2t) c3:(g+8,2t+1)
// ===================================================================
__global__ __launch_bounds__(128) void attn_mma(float* __restrict__ out) {
    const int tid  = threadIdx.x;
    const int warp = tid >> 5, lane = tid & 31;
    const int g = lane >> 2, t = lane & 3;
    const int nh = blockIdx.y, n = nh >> 3, h = nh & 7;
    const int q0 = blockIdx.x * 64 + warp * 16;

    const uint32_t* qp = g_qpk + (size_t)nh * 8 * SP;
    const u64* kp2 = g_kp2 + (size_t)nh * SP * 4;     // [tok][4]
    const u64* vp2 = g_vp2 + (size_t)nh * 100 * 64;   // [kt][16][4]

    // ---- Q fragment (plain fp16, pre-scaled)
    uint32_t aq[4];
    aq[0] = qp[(size_t)t * SP + q0 + g];
    aq[1] = qp[(size_t)t * SP + q0 + 8 + g];
    aq[2] = qp[(size_t)(t + 4) * SP + q0 + g];
    aq[3] = qp[(size_t)(t + 4) * SP + q0 + 8 + g];

    float dpv0[4] = {0.f, 0.f, 0.f, 0.f};
    float dpv1[4] = {0.f, 0.f, 0.f, 0.f};
    float ls0 = 0.f, ls1 = 0.f;

    const u64* kA_p = kp2 + (size_t)g * 4 + t;        // token j0+g
    const u64* kB_p = kp2 + (size_t)(8 + g) * 4 + t;  // token j0+8+g
    const u64* vA_p = vp2 + (size_t)g * 4 + t;        // dim g
    const u64* vB_p = vp2 + (size_t)(8 + g) * 4 + t;  // dim 8+g

    #pragma unroll 4
    for (int kt = 0; kt < 100; kt++) {
        // ---- K fragments: 2x LDG.64 (warp-contiguous 256B)
        u64 kA = kA_p[(size_t)kt * 64];
        u64 kB = kB_p[(size_t)kt * 64];

        float d0[4] = {0.f, 0.f, 0.f, 0.f};
        float d1[4] = {0.f, 0.f, 0.f, 0.f};
        mmaf16(d0, aq, (uint32_t)kA, (uint32_t)(kA >> 32));
        mmaf16(d1, aq, (uint32_t)kB, (uint32_t)(kB >> 32));

        // ---- softmax (log2-domain, no max) + P fragment (plain fp16)
        float p00 = ex2f(d0[0]), p01 = ex2f(d0[1]);
        float p02 = ex2f(d0[2]), p03 = ex2f(d0[3]);
        float p10 = ex2f(d1[0]), p11 = ex2f(d1[1]);
        float p12 = ex2f(d1[2]), p13 = ex2f(d1[3]);
        ls0 += p00 + p01 + p10 + p11;
        ls1 += p02 + p03 + p12 + p13;

        uint32_t pa[4];
        pa[0] = f16x2_of(p00, p01);
        pa[1] = f16x2_of(p02, p03);
        pa[2] = f16x2_of(p10, p11);
        pa[3] = f16x2_of(p12, p13);

        // ---- V fragments: 2x LDG.64 + PV
        u64 vA = vA_p[(size_t)kt * 64];
        u64 vB = vB_p[(size_t)kt * 64];
        mmaf16(dpv0, pa, (uint32_t)vA, (uint32_t)(vA >> 32));
        mmaf16(dpv1, pa, (uint32_t)vB, (uint32_t)(vB >> 32));
    }

    // ---- row-sum reduce over quad (lanes sharing g)
    ls0 += __shfl_xor_sync(0xFFFFFFFFu, ls0, 1);
    ls0 += __shfl_xor_sync(0xFFFFFFFFu, ls0, 2);
    ls1 += __shfl_xor_sync(0xFFFFFFFFu, ls1, 1);
    ls1 += __shfl_xor_sync(0xFFFFFFFFu, ls1, 2);
    float inv0 = 1.f / ls0, inv1 = 1.f / ls1;

    // ---- store fp32 [n][c][s]
    float* ob = out + ((size_t)n * CIN + h * HD) * SP;
    #pragma unroll
    for (int db = 0; db < 2; db++) {
        const float* dpv = db ? dpv1 : dpv0;
        int d = db * 8 + 2 * t;
        ob[(size_t)d * SP + q0 + g]           = dpv[0] * inv0;
        ob[(size_t)(d + 1) * SP + q0 + g]     = dpv[1] * inv0;
        ob[(size_t)d * SP + q0 + 8 + g]       = dpv[2] * inv1;
        ob[(size_t)(d + 1) * SP + q0 + 8 + g] = dpv[3] * inv1;
    }
}

// ===================================================================
extern "C" void kernel_launch(void* const* d_in, const int* in_sizes, int n_in,
                              void* d_out, int out_size) {
    const float* x     = (const float*)d_in[0];
    const float* w_qkv = (const float*)d_in[1];
    const float* w_o   = (const float*)d_in[2];
    const float* b_o   = (const float*)d_in[3];
    float* out = (float*)d_out;

    float* att_ptr;
    cudaGetSymbolAddress((void**)&att_ptr, g_att);

    dim3 blk(16, 16);
    proj_qkv_pack<<<dim3(SP / 64, 384 / 64, NB), blk>>>(w_qkv, x);
    attn_mma<<<dim3(25, NB * NHEAD), 128>>>(att_ptr);
    proj_out<<<dim3(SP / 64, CIN / 64, NB), blk>>>(w_o, att_ptr, b_o, out);
}

// round 9
// speedup vs baseline: 2.1869x; 1.0665x over previous
#include <cuda_runtime.h>
#include <cuda_fp16.h>
#include <cstdint>

#define NB    8
#define CIN   128
#define SP    1600
#define NHEAD 8
#define HD    16

typedef unsigned long long u64;

// ---- packed f32x2 helpers ----
__device__ __forceinline__ u64 pack2(float lo, float hi) {
    u64 r; asm("mov.b64 %0,{%1,%2};" : "=l"(r) : "f"(lo), "f"(hi)); return r;
}
__device__ __forceinline__ float2 unpack2(u64 v) {
    float2 r; asm("mov.b64 {%0,%1},%2;" : "=f"(r.x), "=f"(r.y) : "l"(v)); return r;
}
__device__ __forceinline__ u64 ffma2(u64 a, u64 b, u64 c) {
    u64 d; asm("fma.rn.f32x2 %0,%1,%2,%3;" : "=l"(d) : "l"(a), "l"(b), "l"(c)); return d;
}
__device__ __forceinline__ float ex2f(float x) {
    float y; asm("ex2.approx.f32 %0,%1;" : "=f"(y) : "f"(x)); return y;
}

// f16x2 word: first arg -> low 16 bits, second -> high 16 bits
__device__ __forceinline__ uint32_t f16x2_of(float lo, float hi) {
    uint32_t r;
    asm("cvt.rn.f16x2.f32 %0, %1, %2;" : "=r"(r) : "f"(hi), "f"(lo));
    return r;
}
__device__ __forceinline__ void f16x2_to_f32(uint32_t w, float& lo, float& hi) {
    asm("{ .reg .b16 l, h; mov.b32 {l, h}, %2; cvt.f32.f16 %0, l; cvt.f32.f16 %1, h; }"
        : "=f"(lo), "=f"(hi) : "r"(w));
}
// (a,b) -> main f16x2 | resid f16x2 << 32
__device__ __forceinline__ u64 packh2(float a, float b) {
    uint32_t hw = f16x2_of(a, b);
    float ha, hb;
    f16x2_to_f32(hw, ha, hb);
    uint32_t lw = f16x2_of(a - ha, b - hb);
    return (u64)hw | ((u64)lw << 32);
}

// warp mma: D += A(f16 16x16) * B(f16 16x8), f32 accum
__device__ __forceinline__ void mmaf16(float* d, const uint32_t* a, uint32_t b0, uint32_t b1) {
    asm volatile("mma.sync.aligned.m16n8k16.row.col.f32.f16.f16.f32 "
        "{%0,%1,%2,%3},{%4,%5,%6,%7},{%8,%9},{%0,%1,%2,%3};"
        : "+f"(d[0]), "+f"(d[1]), "+f"(d[2]), "+f"(d[3])
        : "r"(a[0]), "r"(a[1]), "r"(a[2]), "r"(a[3]), "r"(b0), "r"(b1));
}

// Scratch:
__device__ u64      g_wpk[(size_t)384 * 64];            // w_qkv hi/lo [o][cpair]
__device__ u64      g_xpk[(size_t)NB * 64 * SP];        // x hi/lo [n][cpair][s]
__device__ uint32_t g_qpk[(size_t)64 * 8 * SP + 64];    // Q f16x2 [nh][dpair][s] (+pad)
__device__ u64      g_kp2[(size_t)64 * SP * 4];         // K frag words [nh][tok][4]
__device__ u64      g_vp2[(size_t)64 * 100 * 16 * 4];   // V frag words [nh][kt][dim][4]
__device__ float    g_att[(size_t)NB * CIN * SP];

// ===================================================================
// Conversion kernels: fp32 -> fp16 hi/lo u64 words.
// ===================================================================
__global__ void conv_w(const float* __restrict__ W) {   // [384][128]
    int idx = blockIdx.x * 256 + threadIdx.x;           // o*64 + cp
    if (idx >= 384 * 64) return;
    int o = idx >> 6, cp = idx & 63;
    g_wpk[idx] = packh2(W[o * CIN + 2 * cp], W[o * CIN + 2 * cp + 1]);
}

__global__ void conv_x(const float* __restrict__ X) {   // [n][128][1600]
    int idx = blockIdx.x * 256 + threadIdx.x;
    if (idx >= NB * 64 * (SP / 4)) return;
    int s4 = idx % (SP / 4);
    int rest = idx / (SP / 4);
    int cp = rest & 63, n = rest >> 6;
    const float* x0 = X + ((size_t)n * CIN + 2 * cp) * SP + s4 * 4;
    const float* x1 = x0 + SP;
    float4 a = *(const float4*)x0;
    float4 b = *(const float4*)x1;
    u64* dst = g_xpk + ((size_t)n * 64 + cp) * SP + s4 * 4;
    dst[0] = packh2(a.x, b.x);
    dst[1] = packh2(a.y, b.y);
    dst[2] = packh2(a.z, b.z);
    dst[3] = packh2(a.w, b.w);
}

// ===================================================================
// QKV projection on fp16 mma (3-term hi/lo) + pack epilogue.
// CTA: 128 threads (4 warps), 64o x 64s tile.
// ===================================================================
__global__ __launch_bounds__(128) void proj_qkv_mma(void) {
    __shared__ float Ys[64][68];

    const int n  = blockIdx.z;
    const int s0 = blockIdx.x * 64;
    const int o0 = blockIdx.y * 64;
    const int tid = threadIdx.x;
    const int warp = tid >> 5, lane = tid & 31;
    const int g = lane >> 2, t = lane & 3;

    const u64* Wp = g_wpk;
    const u64* Xp = g_xpk + (size_t)n * 64 * SP;

    float d[8][4];
    #pragma unroll
    for (int nb = 0; nb < 8; nb++)
        #pragma unroll
        for (int j = 0; j < 4; j++) d[nb][j] = 0.f;

    const int r1 = o0 + warp * 16 + g;
    const int r2 = r1 + 8;

    #pragma unroll
    for (int ks = 0; ks < 8; ks++) {            // k-step of 16 channels
        const int cp0 = ks * 8;
        u64 wA0 = Wp[(size_t)r1 * 64 + cp0 + t];
        u64 wA1 = Wp[(size_t)r2 * 64 + cp0 + t];
        u64 wA2 = Wp[(size_t)r1 * 64 + cp0 + 4 + t];
        u64 wA3 = Wp[(size_t)r2 * 64 + cp0 + 4 + t];
        uint32_t ah[4] = {(uint32_t)wA0, (uint32_t)wA1, (uint32_t)wA2, (uint32_t)wA3};
        uint32_t al[4] = {(uint32_t)(wA0 >> 32), (uint32_t)(wA1 >> 32),
                          (uint32_t)(wA2 >> 32), (uint32_t)(wA3 >> 32)};

        const u64* xr0 = Xp + (size_t)(cp0 + t) * SP + s0 + g;
        const u64* xr1 = Xp + (size_t)(cp0 + 4 + t) * SP + s0 + g;
        #pragma unroll
        for (int nb = 0; nb < 8; nb++) {
            u64 x0 = xr0[nb * 8];
            u64 x1 = xr1[nb * 8];
            uint32_t bh0 = (uint32_t)x0, bh1 = (uint32_t)x1;
            uint32_t bl0 = (uint32_t)(x0 >> 32), bl1 = (uint32_t)(x1 >> 32);
            mmaf16(d[nb], ah, bh0, bh1);
            mmaf16(d[nb], ah, bl0, bl1);
            mmaf16(d[nb], al, bh0, bh1);
        }
    }

    // stage D to SMEM: c0=(g,2t) c1=(g,2t+1) c2=(g+8,2t) c3=(g+8,2t+1)
    #pragma unroll
    for (int nb = 0; nb < 8; nb++) {
        int ol = warp * 16;
        int sl = nb * 8 + 2 * t;
        Ys[ol + g][sl]     = d[nb][0];
        Ys[ol + g][sl + 1] = d[nb][1];
        Ys[ol + 8 + g][sl]     = d[nb][2];
        Ys[ol + 8 + g][sl + 1] = d[nb][3];
    }
    __syncthreads();

    // ---- pack epilogue: 128 threads, each packs 4 o-pairs x 4 tokens ----
    const int tx = tid & 15, ty = tid >> 4;   // ty in 0..7
    const float qs = 0.25f * 1.4426950408889634f;

    #pragma unroll
    for (int p = 0; p < 4; p++) {
        int olo = ty * 8 + 2 * p;          // even, covers 0..62
        int o = o0 + olo;
        int hh = o / 48;
        int within = o - hh * 48;
        int nhI = n * 8 + hh;
        float r0[4], r1[4];
        #pragma unroll
        for (int j = 0; j < 4; j++) {
            r0[j] = Ys[olo][tx * 4 + j];
            r1[j] = Ys[olo + 1][tx * 4 + j];
        }
        int tok0 = s0 + tx * 4;
        if (within < 16) {
            int dp = within >> 1;
            uint32_t* dst = g_qpk + ((size_t)nhI * 8 + dp) * SP + tok0;
            #pragma unroll
            for (int j = 0; j < 4; j++)
                dst[j] = f16x2_of(r0[j] * qs, r1[j] * qs);
        } else if (within < 32) {
            int dp = (within - 16) >> 1;
            uint32_t* kb = (uint32_t*)g_kp2 + (size_t)nhI * SP * 8;
            int off = (dp & 3) * 2 + (dp >> 2);
            #pragma unroll
            for (int j = 0; j < 4; j++)
                kb[(size_t)(tok0 + j) * 8 + off] = f16x2_of(r0[j], r1[j]);
        } else {
            int dl = within - 32;
            uint32_t* vb = (uint32_t*)g_vp2 + (size_t)nhI * 100 * 128;
            int kt  = tok0 >> 4;
            int kpl = (tok0 >> 1) & 7;
            size_t base = (size_t)kt * 128;
            vb[base + ((size_t)dl * 4 + (kpl & 3)) * 2 + (kpl >> 2)]             = f16x2_of(r0[0], r0[1]);
            vb[base + ((size_t)dl * 4 + ((kpl + 1) & 3)) * 2 + ((kpl + 1) >> 2)] = f16x2_of(r0[2], r0[3]);
            vb[base + ((size_t)(dl + 1) * 4 + (kpl & 3)) * 2 + (kpl >> 2)]             = f16x2_of(r1[0], r1[1]);
            vb[base + ((size_t)(dl + 1) * 4 + ((kpl + 1) & 3)) * 2 + ((kpl + 1) >> 2)] = f16x2_of(r1[2], r1[3]);
        }
    }
}

// ===================================================================
// Output projection (FFMA2, with bias).
// ===================================================================
__global__ void proj_out(const float* __restrict__ W,
                         const float* __restrict__ X,
                         const float* __restrict__ bias,
                         float* __restrict__ Y) {
    __shared__ float Ws[16][64 + 4];
    __shared__ float Xs[16][64 + 4];

    const int n  = blockIdx.z;
    const int s0 = blockIdx.x * 64;
    const int o0 = blockIdx.y * 64;
    const int tx = threadIdx.x, ty = threadIdx.y;
    const int tid = ty * 16 + tx;
    const float* Xn = X + (size_t)n * CIN * SP;

    u64 acc2[2][4];
    #pragma unroll
    for (int p = 0; p < 2; p++)
        #pragma unroll
        for (int j = 0; j < 4; j++) acc2[p][j] = 0ull;

    for (int k0 = 0; k0 < CIN; k0 += 16) {
        #pragma unroll
        for (int r = 0; r < 4; r++) {
            int idx = tid + r * 256;
            int oo = idx >> 4, kc = idx & 15;
            Ws[kc][oo] = W[(size_t)(o0 + oo) * CIN + k0 + kc];
            int kc2 = idx >> 6, ss = idx & 63;
            Xs[kc2][ss] = Xn[(size_t)(k0 + kc2) * SP + s0 + ss];
        }
        __syncthreads();
        #pragma unroll
        for (int kc = 0; kc < 16; kc++) {
            ulonglong2 wv = *(const ulonglong2*)&Ws[kc][ty * 4];
            float4 xv = *(const float4*)&Xs[kc][tx * 4];
            u64 x0 = pack2(xv.x, xv.x), x1 = pack2(xv.y, xv.y);
            u64 x2 = pack2(xv.z, xv.z), x3 = pack2(xv.w, xv.w);
            acc2[0][0] = ffma2(wv.x, x0, acc2[0][0]);
            acc2[0][1] = ffma2(wv.x, x1, acc2[0][1]);
            acc2[0][2] = ffma2(wv.x, x2, acc2[0][2]);
            acc2[0][3] = ffma2(wv.x, x3, acc2[0][3]);
            acc2[1][0] = ffma2(wv.y, x0, acc2[1][0]);
            acc2[1][1] = ffma2(wv.y, x1, acc2[1][1]);
            acc2[1][2] = ffma2(wv.y, x2, acc2[1][2]);
            acc2[1][3] = ffma2(wv.y, x3, acc2[1][3]);
        }
        __syncthreads();
    }

    #pragma unroll
    for (int p = 0; p < 2; p++) {
        int o = o0 + ty * 4 + 2 * p;
        float b0 = bias[o], b1 = bias[o + 1];
        float r0[4], r1[4];
        #pragma unroll
        for (int j = 0; j < 4; j++) {
            float2 v = unpack2(acc2[p][j]);
            r0[j] = v.x + b0; r1[j] = v.y + b1;
        }
        float* y0 = Y + ((size_t)n * CIN + o) * SP + s0 + tx * 4;
        *(float4*)y0 = make_float4(r0[0], r0[1], r0[2], r0[3]);
        *(float4*)(y0 + SP) = make_float4(r1[0], r1[1], r1[2], r1[3]);
    }
}

// ===================================================================
// Attention: 32 queries per warp (two A-tiles sharing K/V loads).
// CTA = 4 warps = 128 queries; grid.x = 13 (store-guarded tail).
// ===================================================================
__global__ __launch_bounds__(128) void attn_mma(float* __restrict__ out) {
    const int tid  = threadIdx.x;
    const int warp = tid >> 5, lane = tid & 31;
    const int g = lane >> 2, t = lane & 3;
    const int nh = blockIdx.y, n = nh >> 3, h = nh & 7;
    const int q0 = blockIdx.x * 128 + warp * 32;     // tiles at q0, q0+16

    const uint32_t* qp = g_qpk + (size_t)nh * 8 * SP;
    const u64* kp2 = g_kp2 + (size_t)nh * SP * 4;
    const u64* vp2 = g_vp2 + (size_t)nh * 100 * 64;

    // ---- two Q fragments
    uint32_t aq0[4], aq1[4];
    {
        const uint32_t* q1 = qp + (size_t)t * SP;
        const uint32_t* q2 = qp + (size_t)(t + 4) * SP;
        aq0[0] = q1[q0 + g];      aq0[1] = q1[q0 + 8 + g];
        aq0[2] = q2[q0 + g];      aq0[3] = q2[q0 + 8 + g];
        aq1[0] = q1[q0 + 16 + g]; aq1[1] = q1[q0 + 24 + g];
        aq1[2] = q2[q0 + 16 + g]; aq1[3] = q2[q0 + 24 + g];
    }

    float dA0[4] = {0,0,0,0}, dA1[4] = {0,0,0,0};    // tile0 dims 0-7 / 8-15
    float dB0[4] = {0,0,0,0}, dB1[4] = {0,0,0,0};    // tile1
    float lsA0 = 0.f, lsA1 = 0.f, lsB0 = 0.f, lsB1 = 0.f;

    const u64* kA_p = kp2 + (size_t)g * 4 + t;
    const u64* kB_p = kp2 + (size_t)(8 + g) * 4 + t;
    const u64* vA_p = vp2 + (size_t)g * 4 + t;
    const u64* vB_p = vp2 + (size_t)(8 + g) * 4 + t;

    #pragma unroll 2
    for (int kt = 0; kt < 100; kt++) {
        u64 kA = kA_p[(size_t)kt * 64];
        u64 kB = kB_p[(size_t)kt * 64];

        float s00[4] = {0,0,0,0}, s01[4] = {0,0,0,0};
        float s10[4] = {0,0,0,0}, s11[4] = {0,0,0,0};
        mmaf16(s00, aq0, (uint32_t)kA, (uint32_t)(kA >> 32));
        mmaf16(s01, aq0, (uint32_t)kB, (uint32_t)(kB >> 32));
        mmaf16(s10, aq1, (uint32_t)kA, (uint32_t)(kA >> 32));
        mmaf16(s11, aq1, (uint32_t)kB, (uint32_t)(kB >> 32));

        float pA00 = ex2f(s00[0]), pA01 = ex2f(s00[1]);
        float pA02 = ex2f(s00[2]), pA03 = ex2f(s00[3]);
        float pA10 = ex2f(s01[0]), pA11 = ex2f(s01[1]);
        float pA12 = ex2f(s01[2]), pA13 = ex2f(s01[3]);
        float pB00 = ex2f(s10[0]), pB01 = ex2f(s10[1]);
        float pB02 = ex2f(s10[2]), pB03 = ex2f(s10[3]);
        float pB10 = ex2f(s11[0]), pB11 = ex2f(s11[1]);
        float pB12 = ex2f(s11[2]), pB13 = ex2f(s11[3]);

        lsA0 += pA00 + pA01 + pA10 + pA11;
        lsA1 += pA02 + pA03 + pA12 + pA13;
        lsB0 += pB00 + pB01 + pB10 + pB11;
        lsB1 += pB02 + pB03 + pB12 + pB13;

        uint32_t paA[4], paB[4];
        paA[0] = f16x2_of(pA00, pA01);
        paA[1] = f16x2_of(pA02, pA03);
        paA[2] = f16x2_of(pA10, pA11);
        paA[3] = f16x2_of(pA12, pA13);
        paB[0] = f16x2_of(pB00, pB01);
        paB[1] = f16x2_of(pB02, pB03);
        paB[2] = f16x2_of(pB10, pB11);
        paB[3] = f16x2_of(pB12, pB13);

        u64 vA = vA_p[(size_t)kt * 64];
        u64 vB = vB_p[(size_t)kt * 64];
        mmaf16(dA0, paA, (uint32_t)vA, (uint32_t)(vA >> 32));
        mmaf16(dA1, paA, (uint32_t)vB, (uint32_t)(vB >> 32));
        mmaf16(dB0, paB, (uint32_t)vA, (uint32_t)(vA >> 32));
        mmaf16(dB1, paB, (uint32_t)vB, (uint32_t)(vB >> 32));
    }

    // ---- quad reduce of row sums
    #pragma unroll
    for (int m = 1; m <= 2; m <<= 1) {
        lsA0 += __shfl_xor_sync(0xFFFFFFFFu, lsA0, m);
        lsA1 += __shfl_xor_sync(0xFFFFFFFFu, lsA1, m);
        lsB0 += __shfl_xor_sync(0xFFFFFFFFu, lsB0, m);
        lsB1 += __shfl_xor_sync(0xFFFFFFFFu, lsB1, m);
    }
    float iA0 = 1.f / lsA0, iA1 = 1.f / lsA1;
    float iB0 = 1.f / lsB0, iB1 = 1.f / lsB1;

    float* ob = out + ((size_t)n * CIN + h * HD) * SP;
    #pragma unroll
    for (int tile = 0; tile < 2; tile++) {
        int qb = q0 + tile * 16;
        if (qb + g >= SP) continue;
        const float* d0 = tile ? dB0 : dA0;
        const float* d1 = tile ? dB1 : dA1;
        float i0 = tile ? iB0 : iA0;
        float i1 = tile ? iB1 : iA1;
        int dd = 2 * t;
        ob[(size_t)dd * SP + qb + g]           = d0[0] * i0;
        ob[(size_t)(dd + 1) * SP + qb + g]     = d0[1] * i0;
        ob[(size_t)(8 + dd) * SP + qb + g]     = d1[0] * i0;
        ob[(size_t)(9 + dd) * SP + qb + g]     = d1[1] * i0;
        if (qb + 8 + g < SP) {
            ob[(size_t)dd * SP + qb + 8 + g]       = d0[2] * i1;
            ob[(size_t)(dd + 1) * SP + qb + 8 + g] = d0[3] * i1;
            ob[(size_t)(8 + dd) * SP + qb + 8 + g] = d1[2] * i1;
            ob[(size_t)(9 + dd) * SP + qb + 8 + g] = d1[3] * i1;
        }
    }
}

// ===================================================================
extern "C" void kernel_launch(void* const* d_in, const int* in_sizes, int n_in,
                              void* d_out, int out_size) {
    const float* x     = (const float*)d_in[0];
    const float* w_qkv = (const float*)d_in[1];
    const float* w_o   = (const float*)d_in[2];
    const float* b_o   = (const float*)d_in[3];
    float* out = (float*)d_out;

    float* att_ptr;
    cudaGetSymbolAddress((void**)&att_ptr, g_att);

    conv_w<<<(384 * 64 + 255) / 256, 256>>>(w_qkv);
    conv_x<<<(NB * 64 * (SP / 4) + 255) / 256, 256>>>(x);
    proj_qkv_mma<<<dim3(SP / 64, 384 / 64, NB), 128>>>();
    attn_mma<<<dim3(13, NB * NHEAD), 128>>>(att_ptr);
    proj_out<<<dim3(SP / 64, CIN / 64, NB), dim3(16, 16)>>>(w_o, att_ptr, b_o, out);
}

// round 10
// speedup vs baseline: 2.5081x; 1.1469x over previous
#include <cuda_runtime.h>
#include <cuda_fp16.h>
#include <cstdint>

#define NB    8
#define CIN   128
#define SP    1600
#define NHEAD 8
#define HD    16

typedef unsigned long long u64;

#define ONESH2 0x3C003C00u   // f16x2 (1.0, 1.0)

// ---- packed f32x2 helpers ----
__device__ __forceinline__ u64 pack2(float lo, float hi) {
    u64 r; asm("mov.b64 %0,{%1,%2};" : "=l"(r) : "f"(lo), "f"(hi)); return r;
}
__device__ __forceinline__ float2 unpack2(u64 v) {
    float2 r; asm("mov.b64 {%0,%1},%2;" : "=f"(r.x), "=f"(r.y) : "l"(v)); return r;
}
__device__ __forceinline__ u64 ffma2(u64 a, u64 b, u64 c) {
    u64 d; asm("fma.rn.f32x2 %0,%1,%2,%3;" : "=l"(d) : "l"(a), "l"(b), "l"(c)); return d;
}

// f16x2 word: first arg -> low 16 bits, second -> high 16 bits
__device__ __forceinline__ uint32_t f16x2_of(float lo, float hi) {
    uint32_t r;
    asm("cvt.rn.f16x2.f32 %0, %1, %2;" : "=r"(r) : "f"(hi), "f"(lo));
    return r;
}
__device__ __forceinline__ void f16x2_to_f32(uint32_t w, float& lo, float& hi) {
    asm("{ .reg .b16 l, h; mov.b32 {l, h}, %2; cvt.f32.f16 %0, l; cvt.f32.f16 %1, h; }"
        : "=f"(lo), "=f"(hi) : "r"(w));
}
__device__ __forceinline__ u64 packh2(float a, float b) {
    uint32_t hw = f16x2_of(a, b);
    float ha, hb;
    f16x2_to_f32(hw, ha, hb);
    uint32_t lw = f16x2_of(a - ha, b - hb);
    return (u64)hw | ((u64)lw << 32);
}
// vectorized exp2 on both fp16 halves
__device__ __forceinline__ uint32_t ex2h2(uint32_t w) {
    uint32_t r; asm("ex2.approx.f16x2 %0, %1;" : "=r"(r) : "r"(w)); return r;
}

// warp mma: D += A(f16 16x16) * B(f16 16x8), f32 accum
__device__ __forceinline__ void mmaf16(float* d, const uint32_t* a, uint32_t b0, uint32_t b1) {
    asm volatile("mma.sync.aligned.m16n8k16.row.col.f32.f16.f16.f32 "
        "{%0,%1,%2,%3},{%4,%5,%6,%7},{%8,%9},{%0,%1,%2,%3};"
        : "+f"(d[0]), "+f"(d[1]), "+f"(d[2]), "+f"(d[3])
        : "r"(a[0]), "r"(a[1]), "r"(a[2]), "r"(a[3]), "r"(b0), "r"(b1));
}

// Scratch:
__device__ u64      g_wpk[(size_t)384 * 64];            // w_qkv hi/lo [o][cpair]
__device__ u64      g_wopk[(size_t)128 * 64];           // w_o hi/lo [o][cpair]
__device__ u64      g_xpk[(size_t)NB * 64 * SP];        // x hi/lo [n][cpair][s]
__device__ uint32_t g_qpk[(size_t)64 * 8 * SP + 64];    // Q f16x2 [nh][dpair][s] (+pad)
__device__ u64      g_kp2[(size_t)64 * SP * 4];         // K frag words [nh][tok][4]
__device__ u64      g_vp2[(size_t)64 * 100 * 16 * 4];   // V frag words [nh][kt][dim][4]
__device__ u64      g_opk[(size_t)NB * 64 * SP];        // attn out hi/lo [n][cpair][s]

// ===================================================================
// Conversion kernels: fp32 -> fp16 hi/lo u64 words.
// ===================================================================
__global__ void conv_w(const float* __restrict__ W) {   // [384][128]
    int idx = blockIdx.x * 256 + threadIdx.x;
    if (idx >= 384 * 64) return;
    int o = idx >> 6, cp = idx & 63;
    g_wpk[idx] = packh2(W[o * CIN + 2 * cp], W[o * CIN + 2 * cp + 1]);
}

__global__ void conv_wo(const float* __restrict__ W) {  // [128][128]
    int idx = blockIdx.x * 256 + threadIdx.x;
    if (idx >= 128 * 64) return;
    int o = idx >> 6, cp = idx & 63;
    g_wopk[idx] = packh2(W[o * CIN + 2 * cp], W[o * CIN + 2 * cp + 1]);
}

__global__ void conv_x(const float* __restrict__ X) {   // [n][128][1600]
    int idx = blockIdx.x * 256 + threadIdx.x;
    if (idx >= NB * 64 * (SP / 4)) return;
    int s4 = idx % (SP / 4);
    int rest = idx / (SP / 4);
    int cp = rest & 63, n = rest >> 6;
    const float* x0 = X + ((size_t)n * CIN + 2 * cp) * SP + s4 * 4;
    const float* x1 = x0 + SP;
    float4 a = *(const float4*)x0;
    float4 b = *(const float4*)x1;
    u64* dst = g_xpk + ((size_t)n * 64 + cp) * SP + s4 * 4;
    dst[0] = packh2(a.x, b.x);
    dst[1] = packh2(a.y, b.y);
    dst[2] = packh2(a.z, b.z);
    dst[3] = packh2(a.w, b.w);
}

// ===================================================================
// QKV projection on fp16 mma (3-term hi/lo) + pack epilogue.
// ===================================================================
__global__ __launch_bounds__(128) void proj_qkv_mma(void) {
    __shared__ float Ys[64][68];

    const int n  = blockIdx.z;
    const int s0 = blockIdx.x * 64;
    const int o0 = blockIdx.y * 64;
    const int tid = threadIdx.x;
    const int warp = tid >> 5, lane = tid & 31;
    const int g = lane >> 2, t = lane & 3;

    const u64* Wp = g_wpk;
    const u64* Xp = g_xpk + (size_t)n * 64 * SP;

    float d[8][4];
    #pragma unroll
    for (int nb = 0; nb < 8; nb++)
        #pragma unroll
        for (int j = 0; j < 4; j++) d[nb][j] = 0.f;

    const int r1 = o0 + warp * 16 + g;
    const int r2 = r1 + 8;

    #pragma unroll
    for (int ks = 0; ks < 8; ks++) {
        const int cp0 = ks * 8;
        u64 wA0 = Wp[(size_t)r1 * 64 + cp0 + t];
        u64 wA1 = Wp[(size_t)r2 * 64 + cp0 + t];
        u64 wA2 = Wp[(size_t)r1 * 64 + cp0 + 4 + t];
        u64 wA3 = Wp[(size_t)r2 * 64 + cp0 + 4 + t];
        uint32_t ah[4] = {(uint32_t)wA0, (uint32_t)wA1, (uint32_t)wA2, (uint32_t)wA3};
        uint32_t al[4] = {(uint32_t)(wA0 >> 32), (uint32_t)(wA1 >> 32),
                          (uint32_t)(wA2 >> 32), (uint32_t)(wA3 >> 32)};

        const u64* xr0 = Xp + (size_t)(cp0 + t) * SP + s0 + g;
        const u64* xr1 = Xp + (size_t)(cp0 + 4 + t) * SP + s0 + g;
        #pragma unroll
        for (int nb = 0; nb < 8; nb++) {
            u64 x0 = xr0[nb * 8];
            u64 x1 = xr1[nb * 8];
            mmaf16(d[nb], ah, (uint32_t)x0, (uint32_t)x1);
            mmaf16(d[nb], ah, (uint32_t)(x0 >> 32), (uint32_t)(x1 >> 32));
            mmaf16(d[nb], al, (uint32_t)x0, (uint32_t)x1);
        }
    }

    #pragma unroll
    for (int nb = 0; nb < 8; nb++) {
        int ol = warp * 16;
        int sl = nb * 8 + 2 * t;
        Ys[ol + g][sl]     = d[nb][0];
        Ys[ol + g][sl + 1] = d[nb][1];
        Ys[ol + 8 + g][sl]     = d[nb][2];
        Ys[ol + 8 + g][sl + 1] = d[nb][3];
    }
    __syncthreads();

    // ---- pack epilogue: 128 threads, 4 o-pairs each ----
    const int tx = tid & 15, ty = tid >> 4;   // ty in 0..7
    const float qs = 0.25f * 1.4426950408889634f;

    #pragma unroll
    for (int p = 0; p < 4; p++) {
        int olo = ty * 8 + 2 * p;
        int o = o0 + olo;
        int hh = o / 48;
        int within = o - hh * 48;
        int nhI = n * 8 + hh;
        float r0[4], r1[4];
        #pragma unroll
        for (int j = 0; j < 4; j++) {
            r0[j] = Ys[olo][tx * 4 + j];
            r1[j] = Ys[olo + 1][tx * 4 + j];
        }
        int tok0 = s0 + tx * 4;
        if (within < 16) {
            int dp = within >> 1;
            uint32_t* dst = g_qpk + ((size_t)nhI * 8 + dp) * SP + tok0;
            #pragma unroll
            for (int j = 0; j < 4; j++)
                dst[j] = f16x2_of(r0[j] * qs, r1[j] * qs);
        } else if (within < 32) {
            int dp = (within - 16) >> 1;
            uint32_t* kb = (uint32_t*)g_kp2 + (size_t)nhI * SP * 8;
            int off = (dp & 3) * 2 + (dp >> 2);
            #pragma unroll
            for (int j = 0; j < 4; j++)
                kb[(size_t)(tok0 + j) * 8 + off] = f16x2_of(r0[j], r1[j]);
        } else {
            int dl = within - 32;
            uint32_t* vb = (uint32_t*)g_vp2 + (size_t)nhI * 100 * 128;
            int kt  = tok0 >> 4;
            int kpl = (tok0 >> 1) & 7;
            size_t base = (size_t)kt * 128;
            vb[base + ((size_t)dl * 4 + (kpl & 3)) * 2 + (kpl >> 2)]             = f16x2_of(r0[0], r0[1]);
            vb[base + ((size_t)dl * 4 + ((kpl + 1) & 3)) * 2 + ((kpl + 1) >> 2)] = f16x2_of(r0[2], r0[3]);
            vb[base + ((size_t)(dl + 1) * 4 + (kpl & 3)) * 2 + (kpl >> 2)]             = f16x2_of(r1[0], r1[1]);
            vb[base + ((size_t)(dl + 1) * 4 + ((kpl + 1) & 3)) * 2 + ((kpl + 1) >> 2)] = f16x2_of(r1[2], r1[3]);
        }
    }
}

// ===================================================================
// Output projection on fp16 mma (3-term hi/lo) + bias epilogue.
// ===================================================================
__global__ __launch_bounds__(128) void proj_out_mma(const float* __restrict__ bias,
                                                    float* __restrict__ Y) {
    __shared__ float Ys[64][68];

    const int n  = blockIdx.z;
    const int s0 = blockIdx.x * 64;
    const int o0 = blockIdx.y * 64;
    const int tid = threadIdx.x;
    const int warp = tid >> 5, lane = tid & 31;
    const int g = lane >> 2, t = lane & 3;

    const u64* Wp = g_wopk;
    const u64* Xp = g_opk + (size_t)n * 64 * SP;

    float d[8][4];
    #pragma unroll
    for (int nb = 0; nb < 8; nb++)
        #pragma unroll
        for (int j = 0; j < 4; j++) d[nb][j] = 0.f;

    const int r1 = o0 + warp * 16 + g;
    const int r2 = r1 + 8;

    #pragma unroll
    for (int ks = 0; ks < 8; ks++) {
        const int cp0 = ks * 8;
        u64 wA0 = Wp[(size_t)r1 * 64 + cp0 + t];
        u64 wA1 = Wp[(size_t)r2 * 64 + cp0 + t];
        u64 wA2 = Wp[(size_t)r1 * 64 + cp0 + 4 + t];
        u64 wA3 = Wp[(size_t)r2 * 64 + cp0 + 4 + t];
        uint32_t ah[4] = {(uint32_t)wA0, (uint32_t)wA1, (uint32_t)wA2, (uint32_t)wA3};
        uint32_t al[4] = {(uint32_t)(wA0 >> 32), (uint32_t)(wA1 >> 32),
                          (uint32_t)(wA2 >> 32), (uint32_t)(wA3 >> 32)};

        const u64* xr0 = Xp + (size_t)(cp0 + t) * SP + s0 + g;
        const u64* xr1 = Xp + (size_t)(cp0 + 4 + t) * SP + s0 + g;
        #pragma unroll
        for (int nb = 0; nb < 8; nb++) {
            u64 x0 = xr0[nb * 8];
            u64 x1 = xr1[nb * 8];
            mmaf16(d[nb], ah, (uint32_t)x0, (uint32_t)x1);
            mmaf16(d[nb], ah, (uint32_t)(x0 >> 32), (uint32_t)(x1 >> 32));
            mmaf16(d[nb], al, (uint32_t)x0, (uint32_t)x1);
        }
    }

    #pragma unroll
    for (int nb = 0; nb < 8; nb++) {
        int ol = warp * 16;
        int sl = nb * 8 + 2 * t;
        Ys[ol + g][sl]     = d[nb][0];
        Ys[ol + g][sl + 1] = d[nb][1];
        Ys[ol + 8 + g][sl]     = d[nb][2];
        Ys[ol + 8 + g][sl + 1] = d[nb][3];
    }
    __syncthreads();

    // ---- bias + store epilogue ----
    const int tx = tid & 15, ty = tid >> 4;   // ty 0..7
    #pragma unroll
    for (int r = 0; r < 8; r++) {
        int olo = ty * 8 + r;
        int o = o0 + olo;
        float b = bias[o];
        float4 v = *(const float4*)&Ys[olo][tx * 4];
        v.x += b; v.y += b; v.z += b; v.w += b;
        *(float4*)(Y + ((size_t)n * CIN + o) * SP + s0 + tx * 4) = v;
    }
}

// ===================================================================
// Attention: 32 q/warp, f16x2 exp, l via ones-MMA, packed hi/lo output.
// ===================================================================
__global__ __launch_bounds__(128) void attn_mma(void) {
    const int tid  = threadIdx.x;
    const int warp = tid >> 5, lane = tid & 31;
    const int g = lane >> 2, t = lane & 3;
    const int nh = blockIdx.y, n = nh >> 3, h = nh & 7;
    const int q0 = blockIdx.x * 128 + warp * 32;

    const uint32_t* qp = g_qpk + (size_t)nh * 8 * SP;
    const u64* kp2 = g_kp2 + (size_t)nh * SP * 4;
    const u64* vp2 = g_vp2 + (size_t)nh * 100 * 64;

    uint32_t aq0[4], aq1[4];
    {
        const uint32_t* q1 = qp + (size_t)t * SP;
        const uint32_t* q2 = qp + (size_t)(t + 4) * SP;
        aq0[0] = q1[q0 + g];      aq0[1] = q1[q0 + 8 + g];
        aq0[2] = q2[q0 + g];      aq0[3] = q2[q0 + 8 + g];
        aq1[0] = q1[q0 + 16 + g]; aq1[1] = q1[q0 + 24 + g];
        aq1[2] = q2[q0 + 16 + g]; aq1[3] = q2[q0 + 24 + g];
    }

    float dA0[4] = {0,0,0,0}, dA1[4] = {0,0,0,0};
    float dB0[4] = {0,0,0,0}, dB1[4] = {0,0,0,0};
    float dLA[4] = {0,0,0,0}, dLB[4] = {0,0,0,0};

    const u64* kA_p = kp2 + (size_t)g * 4 + t;
    const u64* kB_p = kp2 + (size_t)(8 + g) * 4 + t;
    const u64* vA_p = vp2 + (size_t)g * 4 + t;
    const u64* vB_p = vp2 + (size_t)(8 + g) * 4 + t;

    #pragma unroll 2
    for (int kt = 0; kt < 100; kt++) {
        u64 kA = kA_p[(size_t)kt * 64];
        u64 kB = kB_p[(size_t)kt * 64];

        float s00[4] = {0,0,0,0}, s01[4] = {0,0,0,0};
        float s10[4] = {0,0,0,0}, s11[4] = {0,0,0,0};
        mmaf16(s00, aq0, (uint32_t)kA, (uint32_t)(kA >> 32));
        mmaf16(s01, aq0, (uint32_t)kB, (uint32_t)(kB >> 32));
        mmaf16(s10, aq1, (uint32_t)kA, (uint32_t)(kA >> 32));
        mmaf16(s11, aq1, (uint32_t)kB, (uint32_t)(kB >> 32));

        // scores -> f16x2 -> exp2 both halves (P fragments directly)
        uint32_t paA[4], paB[4];
        paA[0] = ex2h2(f16x2_of(s00[0], s00[1]));
        paA[1] = ex2h2(f16x2_of(s00[2], s00[3]));
        paA[2] = ex2h2(f16x2_of(s01[0], s01[1]));
        paA[3] = ex2h2(f16x2_of(s01[2], s01[3]));
        paB[0] = ex2h2(f16x2_of(s10[0], s10[1]));
        paB[1] = ex2h2(f16x2_of(s10[2], s10[3]));
        paB[2] = ex2h2(f16x2_of(s11[0], s11[1]));
        paB[3] = ex2h2(f16x2_of(s11[2], s11[3]));

        // exact fp32 row-sums of fp16 P via ones-MMA
        mmaf16(dLA, paA, ONESH2, ONESH2);
        mmaf16(dLB, paB, ONESH2, ONESH2);

        u64 vA = vA_p[(size_t)kt * 64];
        u64 vB = vB_p[(size_t)kt * 64];
        mmaf16(dA0, paA, (uint32_t)vA, (uint32_t)(vA >> 32));
        mmaf16(dA1, paA, (uint32_t)vB, (uint32_t)(vB >> 32));
        mmaf16(dB0, paB, (uint32_t)vA, (uint32_t)(vA >> 32));
        mmaf16(dB1, paB, (uint32_t)vB, (uint32_t)(vB >> 32));
    }

    // ---- packed hi/lo output: [n][cpair][s]
    u64* op = g_opk + (size_t)n * 64 * SP;
    const int cp0 = h * 8 + t;       // dims 2t, 2t+1
    const int cp1 = h * 8 + 4 + t;   // dims 8+2t, 9+2t

    #pragma unroll
    for (int tile = 0; tile < 2; tile++) {
        int qb = q0 + tile * 16;
        const float* d0 = tile ? dB0 : dA0;
        const float* d1 = tile ? dB1 : dA1;
        const float* dL = tile ? dLB : dLA;
        float i0 = 1.f / dL[0];
        float i1 = 1.f / dL[2];
        if (qb + g < SP) {
            op[(size_t)cp0 * SP + qb + g] = packh2(d0[0] * i0, d0[1] * i0);
            op[(size_t)cp1 * SP + qb + g] = packh2(d1[0] * i0, d1[1] * i0);
        }
        if (qb + 8 + g < SP) {
            op[(size_t)cp0 * SP + qb + 8 + g] = packh2(d0[2] * i1, d0[3] * i1);
            op[(size_t)cp1 * SP + qb + 8 + g] = packh2(d1[2] * i1, d1[3] * i1);
        }
    }
}

// ===================================================================
extern "C" void kernel_launch(void* const* d_in, const int* in_sizes, int n_in,
                              void* d_out, int out_size) {
    const float* x     = (const float*)d_in[0];
    const float* w_qkv = (const float*)d_in[1];
    const float* w_o   = (const float*)d_in[2];
    const float* b_o   = (const float*)d_in[3];
    float* out = (float*)d_out;

    conv_w<<<(384 * 64 + 255) / 256, 256>>>(w_qkv);
    conv_wo<<<(128 * 64 + 255) / 256, 256>>>(w_o);
    conv_x<<<(NB * 64 * (SP / 4) + 255) / 256, 256>>>(x);
    proj_qkv_mma<<<dim3(SP / 64, 384 / 64, NB), 128>>>();
    attn_mma<<<dim3(13, NB * NHEAD), 128>>>();
    proj_out_mma<<<dim3(SP / 64, CIN / 64, NB), 128>>>(b_o, out);
}